// round 8
// baseline (speedup 1.0000x reference)
#include <cuda_runtime.h>
#include <cstdint>

#define NN 4096
#define CC 128
#define NELLD 9
#define NSPEC 10
#define NS3 165   /* #monomials p<=q<=i over 9 */
#define NS2 45    /* #monomials p<=q */
#define NSLOT (NS3 + NS2 + 9)  /* 219 */
#define USTRIDE 876  /* floats per species blob: 219*4 */

// ---------------- device scratch (no runtime allocation allowed) ----------------
__device__ float g_xT[CC * NELLD * NN];       // ~18.9 MB: x transposed to [c][i][pos]
__device__ float g_f[4 * CC * NN];            // ~8.4 MB: contraction output [o][c][pos]
__device__ float g_u3s[NS3 * 4 * 4];          // symmetrized U3 [slot][o][k3]
__device__ float g_u2s[NS2 * 4 * 2];          // symmetrized U2 [slot][o][k2]
__device__ float g_u1s[9 * 4];                // U1 [p][o]
__device__ int   g_perm[NN];                  // pos -> node (species-sorted)
__device__ int   g_pspec[NN];                 // pos -> species

// ---------------- kernel 1: sort nodes by species into perm positions -----------
__global__ void bucket_kernel(const int* __restrict__ spec) {
    __shared__ int cnt[NSPEC];
    __shared__ int cur[NSPEC];
    const int tid = threadIdx.x;
    if (tid < NSPEC) cnt[tid] = 0;
    __syncthreads();
    for (int i = tid; i < NN; i += blockDim.x) atomicAdd(&cnt[spec[i]], 1);
    __syncthreads();
    if (tid == 0) {
        int off = 0;
        for (int s = 0; s < NSPEC; ++s) { cur[s] = off; off += cnt[s]; }
    }
    __syncthreads();
    for (int i = tid; i < NN; i += blockDim.x) {
        const int s = spec[i];
        const int pos = atomicAdd(&cur[s], 1);
        g_perm[pos] = i;
        g_pspec[pos] = s;
    }
}

// ---------------- kernel 1c: gather-transpose x -> xT[c*9+i][pos] ---------------
__global__ void transpose_kernel(const float* __restrict__ x) {
    __shared__ float tile[32][33];
    const int pos0 = blockIdx.x * 32;
    const int ci0 = blockIdx.y * 32;
#pragma unroll
    for (int r = threadIdx.y; r < 32; r += 8) {
        const int n = g_perm[pos0 + r];
        tile[r][threadIdx.x] = x[(long)n * (CC * NELLD) + ci0 + threadIdx.x];
    }
    __syncthreads();
#pragma unroll
    for (int r = threadIdx.y; r < 32; r += 8)
        g_xT[(long)(ci0 + r) * NN + pos0 + threadIdx.x] = tile[threadIdx.x][r];
}

// ---------------- kernel 1b: symmetrize U3/U2 over index permutations -----------
__global__ void sym_kernel(
    const float* __restrict__ U3_0e, const float* __restrict__ U3_1o,
    const float* __restrict__ U2_0e, const float* __restrict__ U2_1o,
    const float* __restrict__ U1_0e, const float* __restrict__ U1_1o) {
    const int tid = threadIdx.x;
    for (int slot = tid; slot < NS3; slot += blockDim.x) {
        int t = slot, p = 0, q, i;
        for (p = 0; p < 9; ++p) { int m = 9 - p; int n = m * (m + 1) / 2; if (t < n) break; t -= n; }
        for (q = p; q < 9; ++q) { int n = 9 - q; if (t < n) break; t -= n; }
        i = q + t;
        int pa[6], pb[6], pc[6], np;
        if (p == q && q == i) { np = 1; pa[0] = p; pb[0] = q; pc[0] = i; }
        else if (p == q) { np = 3; pa[0]=p;pb[0]=p;pc[0]=i; pa[1]=p;pb[1]=i;pc[1]=p; pa[2]=i;pb[2]=p;pc[2]=p; }
        else if (q == i) { np = 3; pa[0]=p;pb[0]=q;pc[0]=q; pa[1]=q;pb[1]=p;pc[1]=q; pa[2]=q;pb[2]=q;pc[2]=p; }
        else { np = 6;
            pa[0]=p;pb[0]=q;pc[0]=i; pa[1]=p;pb[1]=i;pc[1]=q;
            pa[2]=q;pb[2]=p;pc[2]=i; pa[3]=q;pb[3]=i;pc[3]=p;
            pa[4]=i;pb[4]=p;pc[4]=q; pa[5]=i;pb[5]=q;pc[5]=p; }
        for (int o = 0; o < 4; ++o) {
            for (int k = 0; k < 4; ++k) {
                float acc = 0.f;
                for (int e = 0; e < np; ++e) {
                    int base = (pa[e] * 81 + pb[e] * 9 + pc[e]) * 4 + k;
                    acc += (o == 0) ? U3_0e[base] : U3_1o[(o - 1) * 729 * 4 + base];
                }
                g_u3s[slot * 16 + o * 4 + k] = acc;
            }
        }
    }
    for (int slot = tid; slot < NS2; slot += blockDim.x) {
        int t = slot, p, q;
        for (p = 0; p < 9; ++p) { int n = 9 - p; if (t < n) break; t -= n; }
        q = p + t;
        for (int o = 0; o < 4; ++o) {
            for (int k = 0; k < 2; ++k) {
                float acc;
                if (o == 0) {
                    acc = U2_0e[(p * 9 + q) * 2 + k];
                    if (p != q) acc += U2_0e[(q * 9 + p) * 2 + k];
                } else {
                    acc = U2_1o[((o - 1) * 81 + p * 9 + q) * 2 + k];
                    if (p != q) acc += U2_1o[((o - 1) * 81 + q * 9 + p) * 2 + k];
                }
                g_u2s[slot * 8 + o * 2 + k] = acc;
            }
        }
    }
    for (int pp = tid; pp < 9; pp += blockDim.x) {
        g_u1s[pp * 4 + 0] = U1_0e[pp];
        g_u1s[pp * 4 + 1] = U1_1o[pp];
        g_u1s[pp * 4 + 2] = U1_1o[9 + pp];
        g_u1s[pp * 4 + 3] = U1_1o[18 + pp];
    }
}

// ---------------- kernel 3: fused precontract + symmetric cubic contraction -----
// Per block: stage sym tables (12.1 KB) + 140 channel weights, compute all 10
// species' ū (35 KB) in smem, then the R5-proven contraction body.
// smem total = 47744 B (fits 48 KB static limit; 4 blocks/SM).
__global__ void __launch_bounds__(256, 4) contract_kernel(
    const float* __restrict__ W3_0e, const float* __restrict__ W2_0e, const float* __restrict__ W1_0e,
    const float* __restrict__ W3_1o, const float* __restrict__ W2_1o, const float* __restrict__ W1_1o) {
    const int c = blockIdx.y;
    const int tid = threadIdx.x;
    __shared__ __align__(16) float sb[11936];
    float* su   = sb;            // 8760: ū, [s][slot][o4]
    float* su3  = sb + 8760;     // 2640
    float* su2  = sb + 11400;    // 360
    float* su1  = sb + 11760;    // 36
    float* sw   = sb + 11796;    // 140

    // stage sym tables + per-channel weights
    for (int i = tid; i < NS3 * 16; i += 256) su3[i] = g_u3s[i];
    for (int i = tid; i < NS2 * 8; i += 256) su2[i] = g_u2s[i];
    if (tid < 36) su1[tid] = g_u1s[tid];
    if (tid < 40) sw[tid] = W3_0e[tid * CC + c];               // [s*4+k]
    else if (tid < 80) sw[tid] = W3_1o[(tid - 40) * CC + c];
    else if (tid < 100) sw[tid] = W2_0e[(tid - 80) * CC + c];  // [s*2+k]
    else if (tid < 120) sw[tid] = W2_1o[(tid - 100) * CC + c];
    else if (tid < 130) sw[tid] = W1_0e[(tid - 120) * CC + c]; // [s]
    else if (tid < 140) sw[tid] = W1_1o[(tid - 130) * CC + c];
    __syncthreads();

    // compute ū for all species into su
    for (int idx = tid; idx < NSPEC * NSLOT; idx += 256) {
        const int s = idx / NSLOT;
        const int t = idx % NSLOT;
        float4 v;
        if (t < NS3) {
            const float* u = su3 + t * 16;
            const float* wa = sw + s * 4;
            const float* wb = sw + 40 + s * 4;
            v.x = u[0] * wa[0] + u[1] * wa[1] + u[2] * wa[2] + u[3] * wa[3];
            v.y = u[4] * wb[0] + u[5] * wb[1] + u[6] * wb[2] + u[7] * wb[3];
            v.z = u[8] * wb[0] + u[9] * wb[1] + u[10] * wb[2] + u[11] * wb[3];
            v.w = u[12] * wb[0] + u[13] * wb[1] + u[14] * wb[2] + u[15] * wb[3];
        } else if (t < NS3 + NS2) {
            const float* u = su2 + (t - NS3) * 8;
            const float* wa = sw + 80 + s * 2;
            const float* wb = sw + 100 + s * 2;
            v.x = u[0] * wa[0] + u[1] * wa[1];
            v.y = u[2] * wb[0] + u[3] * wb[1];
            v.z = u[4] * wb[0] + u[5] * wb[1];
            v.w = u[6] * wb[0] + u[7] * wb[1];
        } else {
            const float* u = su1 + (t - NS3 - NS2) * 4;
            const float wa = sw[120 + s];
            const float wb = sw[130 + s];
            v = make_float4(u[0] * wa, u[1] * wb, u[2] * wb, u[3] * wb);
        }
        reinterpret_cast<float4*>(su + s * USTRIDE)[t] = v;
    }
    __syncthreads();

    const int pos = blockIdx.x * 256 + tid;
    const int s = g_pspec[pos];

    const float4* u3 = reinterpret_cast<const float4*>(su + s * USTRIDE);
    const float4* u2 = u3 + NS3;
    const float4* u1 = u2 + NS2;

    float xr[9];
#pragma unroll
    for (int i = 0; i < 9; ++i) xr[i] = g_xT[(c * 9 + i) * NN + pos];

    float acc[4] = {};
    int s3 = 0, s2 = 0;
#pragma unroll
    for (int p = 0; p < 9; ++p) {
        const float4 v1 = u1[p];
        acc[0] += v1.x * xr[p];
        acc[1] += v1.y * xr[p];
        acc[2] += v1.z * xr[p];
        acc[3] += v1.w * xr[p];
#pragma unroll
        for (int q = p; q < 9; ++q) {
            const float m2 = xr[p] * xr[q];
            const float4 v2 = u2[s2];
            ++s2;
            acc[0] += v2.x * m2;
            acc[1] += v2.y * m2;
            acc[2] += v2.z * m2;
            acc[3] += v2.w * m2;
#pragma unroll
            for (int i = q; i < 9; ++i) {
                const float4 v3 = u3[s3];
                ++s3;
                const float m = m2 * xr[i];
                acc[0] += v3.x * m;
                acc[1] += v3.y * m;
                acc[2] += v3.z * m;
                acc[3] += v3.w * m;
            }
        }
    }
#pragma unroll
    for (int o = 0; o < 4; ++o)
        g_f[(o * CC + c) * NN + pos] = acc[o];
}

// ---------------- kernel 4: e3nn Linear (64pos x 64m tiles, 4x4 micro) -----------
__global__ void __launch_bounds__(256) linear_kernel(
    const float* __restrict__ W0, const float* __restrict__ W1,
    const float* __restrict__ bias, float* __restrict__ out) {
    const int z = blockIdx.z;
    const int m0 = blockIdx.y * 64;
    const int p0 = blockIdx.x * 64;
    const float* A = g_f + z * (CC * NN);      // [c][pos]
    const float* B = (z == 0) ? W0 : W1;       // [c][m]
    __shared__ float As[32][64];
    __shared__ float Bs[32][64];
    const int tid = threadIdx.x;
    const int r = tid >> 4;            // 0..15 : pos-group of 4
    const int cm = tid & 15;           // 0..15 : m-group of 4
    const int lr = tid >> 4, lc = (tid & 15) << 2;
    float acc[4][4] = {};
#pragma unroll
    for (int kc = 0; kc < CC; kc += 32) {
        *reinterpret_cast<float4*>(&As[lr][lc]) =
            *reinterpret_cast<const float4*>(A + (kc + lr) * NN + p0 + lc);
        *reinterpret_cast<float4*>(&As[lr + 16][lc]) =
            *reinterpret_cast<const float4*>(A + (kc + lr + 16) * NN + p0 + lc);
        *reinterpret_cast<float4*>(&Bs[lr][lc]) =
            *reinterpret_cast<const float4*>(B + (kc + lr) * CC + m0 + lc);
        *reinterpret_cast<float4*>(&Bs[lr + 16][lc]) =
            *reinterpret_cast<const float4*>(B + (kc + lr + 16) * CC + m0 + lc);
        __syncthreads();
#pragma unroll
        for (int k = 0; k < 32; ++k) {
            const float4 a4 = *reinterpret_cast<const float4*>(&As[k][r * 4]);
            const float4 b4 = *reinterpret_cast<const float4*>(&Bs[k][cm * 4]);
            const float a[4] = {a4.x, a4.y, a4.z, a4.w};
            const float b[4] = {b4.x, b4.y, b4.z, b4.w};
#pragma unroll
            for (int i = 0; i < 4; ++i)
#pragma unroll
                for (int j = 0; j < 4; ++j) acc[i][j] += a[i] * b[j];
        }
        __syncthreads();
    }
    const float scale = 0.088388347648318447f;  // 1/sqrt(128)
#pragma unroll
    for (int i = 0; i < 4; ++i) {
        const int n = g_perm[p0 + r * 4 + i];
#pragma unroll
        for (int j = 0; j < 4; ++j) {
            const int m = m0 + cm * 4 + j;
            const float v = acc[i][j] * scale;
            if (z == 0)
                out[n * 512 + m] = v + bias[m];
            else
                out[n * 512 + 128 + m * 3 + (z - 1)] = v;
        }
    }
}

// ---------------- launch ---------------------------------------------------------
extern "C" void kernel_launch(void* const* d_in, const int* in_sizes, int n_in,
                              void* d_out, int out_size) {
    const float* x     = (const float*)d_in[0];
    const int*   spec  = (const int*)d_in[1];
    const float* U3_0e = (const float*)d_in[2];
    const float* U2_0e = (const float*)d_in[3];
    const float* U1_0e = (const float*)d_in[4];
    const float* W3_0e = (const float*)d_in[5];
    const float* W2_0e = (const float*)d_in[6];
    const float* W1_0e = (const float*)d_in[7];
    const float* U3_1o = (const float*)d_in[8];
    const float* U2_1o = (const float*)d_in[9];
    const float* U1_1o = (const float*)d_in[10];
    const float* W3_1o = (const float*)d_in[11];
    const float* W2_1o = (const float*)d_in[12];
    const float* W1_1o = (const float*)d_in[13];
    const float* Wl0   = (const float*)d_in[14];
    const float* Wl1   = (const float*)d_in[15];
    const float* bias  = (const float*)d_in[16];
    float* out = (float*)d_out;

    bucket_kernel<<<1, 1024>>>(spec);
    sym_kernel<<<1, 256>>>(U3_0e, U3_1o, U2_0e, U2_1o, U1_0e, U1_1o);
    transpose_kernel<<<dim3(NN / 32, CC * NELLD / 32), dim3(32, 8)>>>(x);
    contract_kernel<<<dim3(NN / 256, CC), 256>>>(W3_0e, W2_0e, W1_0e,
                                                 W3_1o, W2_1o, W1_1o);
    linear_kernel<<<dim3(NN / 64, 2, 4), 256>>>(Wl0, Wl1, bias, out);
}

// round 9
// speedup vs baseline: 1.1582x; 1.1582x over previous
#include <cuda_runtime.h>
#include <cstdint>

#define NN 4096
#define CC 128
#define NELLD 9
#define NSPEC 10
#define NS3 165   /* #monomials p<=q<=i over 9 */
#define NS2 45    /* #monomials p<=q */
#define NSLOT (NS3 + NS2 + 9)  /* 219 */
#define USTRIDE 876  /* floats per species blob: 219*4 */

// ---------------- device scratch (no runtime allocation allowed) ----------------
__device__ float g_xT[CC * NELLD * NN];       // ~18.9 MB: x transposed to [c][i][pos]
__device__ float g_f[4 * CC * NN];            // ~8.4 MB: contraction output [o][c][pos]
__device__ float g_u3s[16 * NS3];             // symmetrized U3, TRANSPOSED [o*4+k][slot]
__device__ float g_u2s[8 * NS2];              // symmetrized U2, TRANSPOSED [o*2+k][slot]
__device__ float g_u1s[4 * 9];                // U1 [o][p]
__device__ int   g_perm[NN];                  // pos -> node (species-sorted)
__device__ int   g_pspec[NN];                 // pos -> species

// ---------------- kernel 1: sort nodes by species into perm positions -----------
__global__ void bucket_kernel(const int* __restrict__ spec) {
    __shared__ int cnt[NSPEC];
    __shared__ int cur[NSPEC];
    const int tid = threadIdx.x;
    if (tid < NSPEC) cnt[tid] = 0;
    __syncthreads();
    for (int i = tid; i < NN; i += blockDim.x) atomicAdd(&cnt[spec[i]], 1);
    __syncthreads();
    if (tid == 0) {
        int off = 0;
        for (int s = 0; s < NSPEC; ++s) { cur[s] = off; off += cnt[s]; }
    }
    __syncthreads();
    for (int i = tid; i < NN; i += blockDim.x) {
        const int s = spec[i];
        const int pos = atomicAdd(&cur[s], 1);
        g_perm[pos] = i;
        g_pspec[pos] = s;
    }
}

// ---------------- kernel 1c: gather-transpose x -> xT[c*9+i][pos] ---------------
__global__ void transpose_kernel(const float* __restrict__ x) {
    __shared__ float tile[32][33];
    const int pos0 = blockIdx.x * 32;
    const int ci0 = blockIdx.y * 32;
#pragma unroll
    for (int r = threadIdx.y; r < 32; r += 8) {
        const int n = g_perm[pos0 + r];
        tile[r][threadIdx.x] = x[(long)n * (CC * NELLD) + ci0 + threadIdx.x];
    }
    __syncthreads();
#pragma unroll
    for (int r = threadIdx.y; r < 32; r += 8)
        g_xT[(long)(ci0 + r) * NN + pos0 + threadIdx.x] = tile[threadIdx.x][r];
}

// ---------------- kernel 1b: symmetrize U3/U2, TRANSPOSED output [j][slot] ------
__global__ void sym_kernel(
    const float* __restrict__ U3_0e, const float* __restrict__ U3_1o,
    const float* __restrict__ U2_0e, const float* __restrict__ U2_1o,
    const float* __restrict__ U1_0e, const float* __restrict__ U1_1o) {
    const int tid = threadIdx.x;
    for (int slot = tid; slot < NS3; slot += blockDim.x) {
        int t = slot, p = 0, q, i;
        for (p = 0; p < 9; ++p) { int m = 9 - p; int n = m * (m + 1) / 2; if (t < n) break; t -= n; }
        for (q = p; q < 9; ++q) { int n = 9 - q; if (t < n) break; t -= n; }
        i = q + t;
        int pa[6], pb[6], pc[6], np;
        if (p == q && q == i) { np = 1; pa[0] = p; pb[0] = q; pc[0] = i; }
        else if (p == q) { np = 3; pa[0]=p;pb[0]=p;pc[0]=i; pa[1]=p;pb[1]=i;pc[1]=p; pa[2]=i;pb[2]=p;pc[2]=p; }
        else if (q == i) { np = 3; pa[0]=p;pb[0]=q;pc[0]=q; pa[1]=q;pb[1]=p;pc[1]=q; pa[2]=q;pb[2]=q;pc[2]=p; }
        else { np = 6;
            pa[0]=p;pb[0]=q;pc[0]=i; pa[1]=p;pb[1]=i;pc[1]=q;
            pa[2]=q;pb[2]=p;pc[2]=i; pa[3]=q;pb[3]=i;pc[3]=p;
            pa[4]=i;pb[4]=p;pc[4]=q; pa[5]=i;pb[5]=q;pc[5]=p; }
        for (int o = 0; o < 4; ++o) {
            for (int k = 0; k < 4; ++k) {
                float acc = 0.f;
                for (int e = 0; e < np; ++e) {
                    int base = (pa[e] * 81 + pb[e] * 9 + pc[e]) * 4 + k;
                    acc += (o == 0) ? U3_0e[base] : U3_1o[(o - 1) * 729 * 4 + base];
                }
                g_u3s[(o * 4 + k) * NS3 + slot] = acc;
            }
        }
    }
    for (int slot = tid; slot < NS2; slot += blockDim.x) {
        int t = slot, p, q;
        for (p = 0; p < 9; ++p) { int n = 9 - p; if (t < n) break; t -= n; }
        q = p + t;
        for (int o = 0; o < 4; ++o) {
            for (int k = 0; k < 2; ++k) {
                float acc;
                if (o == 0) {
                    acc = U2_0e[(p * 9 + q) * 2 + k];
                    if (p != q) acc += U2_0e[(q * 9 + p) * 2 + k];
                } else {
                    acc = U2_1o[((o - 1) * 81 + p * 9 + q) * 2 + k];
                    if (p != q) acc += U2_1o[((o - 1) * 81 + q * 9 + p) * 2 + k];
                }
                g_u2s[(o * 2 + k) * NS2 + slot] = acc;
            }
        }
    }
    for (int pp = tid; pp < 9; pp += blockDim.x) {
        g_u1s[0 * 9 + pp] = U1_0e[pp];
        g_u1s[1 * 9 + pp] = U1_1o[pp];
        g_u1s[2 * 9 + pp] = U1_1o[9 + pp];
        g_u1s[3 * 9 + pp] = U1_1o[18 + pp];
    }
}

// ---------------- kernel 3: fused precontract + symmetric cubic contraction -----
// Prologue: sym tables staged transposed (lane-contiguous -> conflict-free LDS),
// ū for all 10 species computed into smem; then the R5-proven contraction body.
__global__ void __launch_bounds__(256, 4) contract_kernel(
    const float* __restrict__ W3_0e, const float* __restrict__ W2_0e, const float* __restrict__ W1_0e,
    const float* __restrict__ W3_1o, const float* __restrict__ W2_1o, const float* __restrict__ W1_1o) {
    const int c = blockIdx.y;
    const int tid = threadIdx.x;
    __shared__ __align__(16) float sb[11936];
    float* su   = sb;            // 8760: ū, [s][slot][o4]
    float* su3  = sb + 8760;     // 2640: [j][slot], j=0..15
    float* su2  = sb + 11400;    // 360:  [j][slot], j=0..7
    float* su1  = sb + 11760;    // 36:   [o][p]
    float* sw   = sb + 11796;    // 140

    // stage sym tables + per-channel weights (all coalesced / conflict-free)
    for (int i = tid; i < 16 * NS3; i += 256) su3[i] = g_u3s[i];
    for (int i = tid; i < 8 * NS2; i += 256) su2[i] = g_u2s[i];
    if (tid < 36) su1[tid] = g_u1s[tid];
    if (tid < 40) sw[tid] = W3_0e[tid * CC + c];               // [s*4+k]
    else if (tid < 80) sw[tid] = W3_1o[(tid - 40) * CC + c];
    else if (tid < 100) sw[tid] = W2_0e[(tid - 80) * CC + c];  // [s*2+k]
    else if (tid < 120) sw[tid] = W2_1o[(tid - 100) * CC + c];
    else if (tid < 130) sw[tid] = W1_0e[(tid - 120) * CC + c]; // [s]
    else if (tid < 140) sw[tid] = W1_1o[(tid - 130) * CC + c];
    __syncthreads();

    // compute ū for all species; lane t reads column t of transposed tables ->
    // stride-1 across lanes, zero bank conflicts; weights are warp-uniform.
    const int t = tid;  // NSLOT = 219 < 256: single predicated pass per species
#pragma unroll 1
    for (int s = 0; s < NSPEC; ++s) {
        if (t < NSLOT) {
            float4 v;
            if (t < NS3) {
                const float wa0 = sw[s * 4], wa1 = sw[s * 4 + 1], wa2 = sw[s * 4 + 2], wa3 = sw[s * 4 + 3];
                const float wb0 = sw[40 + s * 4], wb1 = sw[41 + s * 4], wb2 = sw[42 + s * 4], wb3 = sw[43 + s * 4];
                v.x = su3[t] * wa0 + su3[NS3 + t] * wa1 + su3[2 * NS3 + t] * wa2 + su3[3 * NS3 + t] * wa3;
                v.y = su3[4 * NS3 + t] * wb0 + su3[5 * NS3 + t] * wb1 + su3[6 * NS3 + t] * wb2 + su3[7 * NS3 + t] * wb3;
                v.z = su3[8 * NS3 + t] * wb0 + su3[9 * NS3 + t] * wb1 + su3[10 * NS3 + t] * wb2 + su3[11 * NS3 + t] * wb3;
                v.w = su3[12 * NS3 + t] * wb0 + su3[13 * NS3 + t] * wb1 + su3[14 * NS3 + t] * wb2 + su3[15 * NS3 + t] * wb3;
            } else if (t < NS3 + NS2) {
                const int t2 = t - NS3;
                const float wa0 = sw[80 + s * 2], wa1 = sw[81 + s * 2];
                const float wb0 = sw[100 + s * 2], wb1 = sw[101 + s * 2];
                v.x = su2[t2] * wa0 + su2[NS2 + t2] * wa1;
                v.y = su2[2 * NS2 + t2] * wb0 + su2[3 * NS2 + t2] * wb1;
                v.z = su2[4 * NS2 + t2] * wb0 + su2[5 * NS2 + t2] * wb1;
                v.w = su2[6 * NS2 + t2] * wb0 + su2[7 * NS2 + t2] * wb1;
            } else {
                const int t1 = t - NS3 - NS2;
                const float wa = sw[120 + s];
                const float wb = sw[130 + s];
                v = make_float4(su1[t1] * wa, su1[9 + t1] * wb, su1[18 + t1] * wb, su1[27 + t1] * wb);
            }
            reinterpret_cast<float4*>(su + s * USTRIDE)[t] = v;
        }
    }
    __syncthreads();

    const int pos = blockIdx.x * 256 + tid;
    const int s = g_pspec[pos];

    const float4* u3 = reinterpret_cast<const float4*>(su + s * USTRIDE);
    const float4* u2 = u3 + NS3;
    const float4* u1 = u2 + NS2;

    float xr[9];
#pragma unroll
    for (int i = 0; i < 9; ++i) xr[i] = g_xT[(c * 9 + i) * NN + pos];

    float acc[4] = {};
    int s3 = 0, s2 = 0;
#pragma unroll
    for (int p = 0; p < 9; ++p) {
        const float4 v1 = u1[p];
        acc[0] += v1.x * xr[p];
        acc[1] += v1.y * xr[p];
        acc[2] += v1.z * xr[p];
        acc[3] += v1.w * xr[p];
#pragma unroll
        for (int q = p; q < 9; ++q) {
            const float m2 = xr[p] * xr[q];
            const float4 v2 = u2[s2];
            ++s2;
            acc[0] += v2.x * m2;
            acc[1] += v2.y * m2;
            acc[2] += v2.z * m2;
            acc[3] += v2.w * m2;
#pragma unroll
            for (int i = q; i < 9; ++i) {
                const float4 v3 = u3[s3];
                ++s3;
                const float m = m2 * xr[i];
                acc[0] += v3.x * m;
                acc[1] += v3.y * m;
                acc[2] += v3.z * m;
                acc[3] += v3.w * m;
            }
        }
    }
#pragma unroll
    for (int o = 0; o < 4; ++o)
        g_f[(o * CC + c) * NN + pos] = acc[o];
}

// ---------------- kernel 4: e3nn Linear (64pos x 64m tiles, 4x4 micro) -----------
__global__ void __launch_bounds__(256) linear_kernel(
    const float* __restrict__ W0, const float* __restrict__ W1,
    const float* __restrict__ bias, float* __restrict__ out) {
    const int z = blockIdx.z;
    const int m0 = blockIdx.y * 64;
    const int p0 = blockIdx.x * 64;
    const float* A = g_f + z * (CC * NN);      // [c][pos]
    const float* B = (z == 0) ? W0 : W1;       // [c][m]
    __shared__ float As[32][64];
    __shared__ float Bs[32][64];
    const int tid = threadIdx.x;
    const int r = tid >> 4;            // 0..15 : pos-group of 4
    const int cm = tid & 15;           // 0..15 : m-group of 4
    const int lr = tid >> 4, lc = (tid & 15) << 2;
    float acc[4][4] = {};
#pragma unroll
    for (int kc = 0; kc < CC; kc += 32) {
        *reinterpret_cast<float4*>(&As[lr][lc]) =
            *reinterpret_cast<const float4*>(A + (kc + lr) * NN + p0 + lc);
        *reinterpret_cast<float4*>(&As[lr + 16][lc]) =
            *reinterpret_cast<const float4*>(A + (kc + lr + 16) * NN + p0 + lc);
        *reinterpret_cast<float4*>(&Bs[lr][lc]) =
            *reinterpret_cast<const float4*>(B + (kc + lr) * CC + m0 + lc);
        *reinterpret_cast<float4*>(&Bs[lr + 16][lc]) =
            *reinterpret_cast<const float4*>(B + (kc + lr + 16) * CC + m0 + lc);
        __syncthreads();
#pragma unroll
        for (int k = 0; k < 32; ++k) {
            const float4 a4 = *reinterpret_cast<const float4*>(&As[k][r * 4]);
            const float4 b4 = *reinterpret_cast<const float4*>(&Bs[k][cm * 4]);
            const float a[4] = {a4.x, a4.y, a4.z, a4.w};
            const float b[4] = {b4.x, b4.y, b4.z, b4.w};
#pragma unroll
            for (int i = 0; i < 4; ++i)
#pragma unroll
                for (int j = 0; j < 4; ++j) acc[i][j] += a[i] * b[j];
        }
        __syncthreads();
    }
    const float scale = 0.088388347648318447f;  // 1/sqrt(128)
#pragma unroll
    for (int i = 0; i < 4; ++i) {
        const int n = g_perm[p0 + r * 4 + i];
#pragma unroll
        for (int j = 0; j < 4; ++j) {
            const int m = m0 + cm * 4 + j;
            const float v = acc[i][j] * scale;
            if (z == 0)
                out[n * 512 + m] = v + bias[m];
            else
                out[n * 512 + 128 + m * 3 + (z - 1)] = v;
        }
    }
}

// ---------------- launch ---------------------------------------------------------
extern "C" void kernel_launch(void* const* d_in, const int* in_sizes, int n_in,
                              void* d_out, int out_size) {
    const float* x     = (const float*)d_in[0];
    const int*   spec  = (const int*)d_in[1];
    const float* U3_0e = (const float*)d_in[2];
    const float* U2_0e = (const float*)d_in[3];
    const float* U1_0e = (const float*)d_in[4];
    const float* W3_0e = (const float*)d_in[5];
    const float* W2_0e = (const float*)d_in[6];
    const float* W1_0e = (const float*)d_in[7];
    const float* U3_1o = (const float*)d_in[8];
    const float* U2_1o = (const float*)d_in[9];
    const float* U1_1o = (const float*)d_in[10];
    const float* W3_1o = (const float*)d_in[11];
    const float* W2_1o = (const float*)d_in[12];
    const float* W1_1o = (const float*)d_in[13];
    const float* Wl0   = (const float*)d_in[14];
    const float* Wl1   = (const float*)d_in[15];
    const float* bias  = (const float*)d_in[16];
    float* out = (float*)d_out;

    bucket_kernel<<<1, 1024>>>(spec);
    sym_kernel<<<1, 256>>>(U3_0e, U3_1o, U2_0e, U2_1o, U1_0e, U1_1o);
    transpose_kernel<<<dim3(NN / 32, CC * NELLD / 32), dim3(32, 8)>>>(x);
    contract_kernel<<<dim3(NN / 256, CC), 256>>>(W3_0e, W2_0e, W1_0e,
                                                 W3_1o, W2_1o, W1_1o);
    linear_kernel<<<dim3(NN / 64, 2, 4), 256>>>(Wl0, Wl1, bias, out);
}

// round 10
// speedup vs baseline: 1.2802x; 1.1054x over previous
#include <cuda_runtime.h>
#include <cstdint>

#define NN 4096
#define CC 128
#define NELLD 9
#define NSPEC 10
#define NS3 165   /* #monomials p<=q<=i over 9 */
#define NS2 45    /* #monomials p<=q */
#define NSLOT (NS3 + NS2 + 9)  /* 219 */
#define USTRIDE 876  /* floats per (c,s): 219*4 */

// ---------------- device scratch (no runtime allocation allowed) ----------------
__device__ float g_u[CC * NSPEC * USTRIDE];   // ~4.5 MB: weighted basis per (c,s), [slot][o4]
__device__ float g_xT[CC * NELLD * NN];       // ~18.9 MB: x transposed to [c][i][pos]
__device__ float g_f[4 * CC * NN];            // ~8.4 MB: contraction output [o][c][pos]
__device__ float g_u3s[16 * NS3];             // symmetrized U3, TRANSPOSED [o*4+k][slot]
__device__ float g_u2s[8 * NS2];              // symmetrized U2, TRANSPOSED [o*2+k][slot]
__device__ float g_u1s[4 * 9];                // U1 [o][p]
__device__ int   g_perm[NN];                  // pos -> node (species-sorted)
__device__ int   g_pspec[NN];                 // pos -> species

// ---------------- kernel 1: sort nodes by species into perm positions -----------
__global__ void bucket_kernel(const int* __restrict__ spec) {
    __shared__ int cnt[NSPEC];
    __shared__ int cur[NSPEC];
    const int tid = threadIdx.x;
    if (tid < NSPEC) cnt[tid] = 0;
    __syncthreads();
    for (int i = tid; i < NN; i += blockDim.x) atomicAdd(&cnt[spec[i]], 1);
    __syncthreads();
    if (tid == 0) {
        int off = 0;
        for (int s = 0; s < NSPEC; ++s) { cur[s] = off; off += cnt[s]; }
    }
    __syncthreads();
    for (int i = tid; i < NN; i += blockDim.x) {
        const int s = spec[i];
        const int pos = atomicAdd(&cur[s], 1);
        g_perm[pos] = i;
        g_pspec[pos] = s;
    }
}

// ---------------- kernel 1c: gather-transpose x -> xT[c*9+i][pos] ---------------
__global__ void transpose_kernel(const float* __restrict__ x) {
    __shared__ float tile[32][33];
    const int pos0 = blockIdx.x * 32;
    const int ci0 = blockIdx.y * 32;
#pragma unroll
    for (int r = threadIdx.y; r < 32; r += 8) {
        const int n = g_perm[pos0 + r];
        tile[r][threadIdx.x] = x[(long)n * (CC * NELLD) + ci0 + threadIdx.x];
    }
    __syncthreads();
#pragma unroll
    for (int r = threadIdx.y; r < 32; r += 8)
        g_xT[(long)(ci0 + r) * NN + pos0 + threadIdx.x] = tile[threadIdx.x][r];
}

// ---------------- kernel 1b: symmetrize U3/U2, TRANSPOSED output [j][slot] ------
__global__ void sym_kernel(
    const float* __restrict__ U3_0e, const float* __restrict__ U3_1o,
    const float* __restrict__ U2_0e, const float* __restrict__ U2_1o,
    const float* __restrict__ U1_0e, const float* __restrict__ U1_1o) {
    const int tid = threadIdx.x;
    for (int slot = tid; slot < NS3; slot += blockDim.x) {
        int t = slot, p = 0, q, i;
        for (p = 0; p < 9; ++p) { int m = 9 - p; int n = m * (m + 1) / 2; if (t < n) break; t -= n; }
        for (q = p; q < 9; ++q) { int n = 9 - q; if (t < n) break; t -= n; }
        i = q + t;
        int pa[6], pb[6], pc[6], np;
        if (p == q && q == i) { np = 1; pa[0] = p; pb[0] = q; pc[0] = i; }
        else if (p == q) { np = 3; pa[0]=p;pb[0]=p;pc[0]=i; pa[1]=p;pb[1]=i;pc[1]=p; pa[2]=i;pb[2]=p;pc[2]=p; }
        else if (q == i) { np = 3; pa[0]=p;pb[0]=q;pc[0]=q; pa[1]=q;pb[1]=p;pc[1]=q; pa[2]=q;pb[2]=q;pc[2]=p; }
        else { np = 6;
            pa[0]=p;pb[0]=q;pc[0]=i; pa[1]=p;pb[1]=i;pc[1]=q;
            pa[2]=q;pb[2]=p;pc[2]=i; pa[3]=q;pb[3]=i;pc[3]=p;
            pa[4]=i;pb[4]=p;pc[4]=q; pa[5]=i;pb[5]=q;pc[5]=p; }
        for (int o = 0; o < 4; ++o) {
            for (int k = 0; k < 4; ++k) {
                float acc = 0.f;
                for (int e = 0; e < np; ++e) {
                    int base = (pa[e] * 81 + pb[e] * 9 + pc[e]) * 4 + k;
                    acc += (o == 0) ? U3_0e[base] : U3_1o[(o - 1) * 729 * 4 + base];
                }
                g_u3s[(o * 4 + k) * NS3 + slot] = acc;
            }
        }
    }
    for (int slot = tid; slot < NS2; slot += blockDim.x) {
        int t = slot, p, q;
        for (p = 0; p < 9; ++p) { int n = 9 - p; if (t < n) break; t -= n; }
        q = p + t;
        for (int o = 0; o < 4; ++o) {
            for (int k = 0; k < 2; ++k) {
                float acc;
                if (o == 0) {
                    acc = U2_0e[(p * 9 + q) * 2 + k];
                    if (p != q) acc += U2_0e[(q * 9 + p) * 2 + k];
                } else {
                    acc = U2_1o[((o - 1) * 81 + p * 9 + q) * 2 + k];
                    if (p != q) acc += U2_1o[((o - 1) * 81 + q * 9 + p) * 2 + k];
                }
                g_u2s[(o * 2 + k) * NS2 + slot] = acc;
            }
        }
    }
    for (int pp = tid; pp < 9; pp += blockDim.x) {
        g_u1s[0 * 9 + pp] = U1_0e[pp];
        g_u1s[1 * 9 + pp] = U1_1o[pp];
        g_u1s[2 * 9 + pp] = U1_1o[9 + pp];
        g_u1s[3 * 9 + pp] = U1_1o[18 + pp];
    }
}

// ---------------- kernel 2: precontract, one block per (channel, species) -------
// 1280 blocks; thread t = slot t; transposed tables read coalesced (L2-hot),
// 12 warp-uniform weight scalars, one coalesced float4 store.
__global__ void __launch_bounds__(256) precompute_kernel(
    const float* __restrict__ W3_0e, const float* __restrict__ W2_0e, const float* __restrict__ W1_0e,
    const float* __restrict__ W3_1o, const float* __restrict__ W2_1o, const float* __restrict__ W1_1o) {
    const int c = blockIdx.x, s = blockIdx.y;
    const int t = threadIdx.x;
    if (t >= NSLOT) return;
    float4 v;
    if (t < NS3) {
        const float wa0 = W3_0e[(s * 4 + 0) * CC + c], wa1 = W3_0e[(s * 4 + 1) * CC + c];
        const float wa2 = W3_0e[(s * 4 + 2) * CC + c], wa3 = W3_0e[(s * 4 + 3) * CC + c];
        const float wb0 = W3_1o[(s * 4 + 0) * CC + c], wb1 = W3_1o[(s * 4 + 1) * CC + c];
        const float wb2 = W3_1o[(s * 4 + 2) * CC + c], wb3 = W3_1o[(s * 4 + 3) * CC + c];
        v.x = g_u3s[t] * wa0 + g_u3s[NS3 + t] * wa1 + g_u3s[2 * NS3 + t] * wa2 + g_u3s[3 * NS3 + t] * wa3;
        v.y = g_u3s[4 * NS3 + t] * wb0 + g_u3s[5 * NS3 + t] * wb1 + g_u3s[6 * NS3 + t] * wb2 + g_u3s[7 * NS3 + t] * wb3;
        v.z = g_u3s[8 * NS3 + t] * wb0 + g_u3s[9 * NS3 + t] * wb1 + g_u3s[10 * NS3 + t] * wb2 + g_u3s[11 * NS3 + t] * wb3;
        v.w = g_u3s[12 * NS3 + t] * wb0 + g_u3s[13 * NS3 + t] * wb1 + g_u3s[14 * NS3 + t] * wb2 + g_u3s[15 * NS3 + t] * wb3;
    } else if (t < NS3 + NS2) {
        const int t2 = t - NS3;
        const float wa0 = W2_0e[(s * 2 + 0) * CC + c], wa1 = W2_0e[(s * 2 + 1) * CC + c];
        const float wb0 = W2_1o[(s * 2 + 0) * CC + c], wb1 = W2_1o[(s * 2 + 1) * CC + c];
        v.x = g_u2s[t2] * wa0 + g_u2s[NS2 + t2] * wa1;
        v.y = g_u2s[2 * NS2 + t2] * wb0 + g_u2s[3 * NS2 + t2] * wb1;
        v.z = g_u2s[4 * NS2 + t2] * wb0 + g_u2s[5 * NS2 + t2] * wb1;
        v.w = g_u2s[6 * NS2 + t2] * wb0 + g_u2s[7 * NS2 + t2] * wb1;
    } else {
        const int t1 = t - NS3 - NS2;
        const float wa = W1_0e[s * CC + c];
        const float wb = W1_1o[s * CC + c];
        v = make_float4(g_u1s[t1] * wa, g_u1s[9 + t1] * wb, g_u1s[18 + t1] * wb, g_u1s[27 + t1] * wb);
    }
    reinterpret_cast<float4*>(g_u + (c * NSPEC + s) * USTRIDE)[t] = v;
}

// ---------------- kernel 3: symmetric cubic-form contraction (R5 verbatim) ------
__global__ void __launch_bounds__(256, 4) contract_kernel() {
    const int c = blockIdx.y;
    __shared__ __align__(16) float su[NSPEC * USTRIDE];

    const float* src = g_u + c * (NSPEC * USTRIDE);
    for (int i = threadIdx.x; i < NSPEC * USTRIDE / 4; i += 256)
        reinterpret_cast<float4*>(su)[i] = reinterpret_cast<const float4*>(src)[i];
    __syncthreads();

    const int pos = blockIdx.x * 256 + threadIdx.x;
    const int s = g_pspec[pos];

    const float4* u3 = reinterpret_cast<const float4*>(su + s * USTRIDE);
    const float4* u2 = u3 + NS3;
    const float4* u1 = u2 + NS2;

    float xr[9];
#pragma unroll
    for (int i = 0; i < 9; ++i) xr[i] = g_xT[(c * 9 + i) * NN + pos];

    float acc[4] = {};
    int s3 = 0, s2 = 0;
#pragma unroll
    for (int p = 0; p < 9; ++p) {
        const float4 v1 = u1[p];
        acc[0] += v1.x * xr[p];
        acc[1] += v1.y * xr[p];
        acc[2] += v1.z * xr[p];
        acc[3] += v1.w * xr[p];
#pragma unroll
        for (int q = p; q < 9; ++q) {
            const float m2 = xr[p] * xr[q];
            const float4 v2 = u2[s2];
            ++s2;
            acc[0] += v2.x * m2;
            acc[1] += v2.y * m2;
            acc[2] += v2.z * m2;
            acc[3] += v2.w * m2;
#pragma unroll
            for (int i = q; i < 9; ++i) {
                const float4 v3 = u3[s3];
                ++s3;
                const float m = m2 * xr[i];
                acc[0] += v3.x * m;
                acc[1] += v3.y * m;
                acc[2] += v3.z * m;
                acc[3] += v3.w * m;
            }
        }
    }
#pragma unroll
    for (int o = 0; o < 4; ++o)
        g_f[(o * CC + c) * NN + pos] = acc[o];
}

// ---------------- kernel 4: e3nn Linear (64pos x 64m tiles, 4x4 micro) -----------
__global__ void __launch_bounds__(256) linear_kernel(
    const float* __restrict__ W0, const float* __restrict__ W1,
    const float* __restrict__ bias, float* __restrict__ out) {
    const int z = blockIdx.z;
    const int m0 = blockIdx.y * 64;
    const int p0 = blockIdx.x * 64;
    const float* A = g_f + z * (CC * NN);      // [c][pos]
    const float* B = (z == 0) ? W0 : W1;       // [c][m]
    __shared__ float As[32][64];
    __shared__ float Bs[32][64];
    const int tid = threadIdx.x;
    const int r = tid >> 4;            // 0..15 : pos-group of 4
    const int cm = tid & 15;           // 0..15 : m-group of 4
    const int lr = tid >> 4, lc = (tid & 15) << 2;
    float acc[4][4] = {};
#pragma unroll
    for (int kc = 0; kc < CC; kc += 32) {
        *reinterpret_cast<float4*>(&As[lr][lc]) =
            *reinterpret_cast<const float4*>(A + (kc + lr) * NN + p0 + lc);
        *reinterpret_cast<float4*>(&As[lr + 16][lc]) =
            *reinterpret_cast<const float4*>(A + (kc + lr + 16) * NN + p0 + lc);
        *reinterpret_cast<float4*>(&Bs[lr][lc]) =
            *reinterpret_cast<const float4*>(B + (kc + lr) * CC + m0 + lc);
        *reinterpret_cast<float4*>(&Bs[lr + 16][lc]) =
            *reinterpret_cast<const float4*>(B + (kc + lr + 16) * CC + m0 + lc);
        __syncthreads();
#pragma unroll
        for (int k = 0; k < 32; ++k) {
            const float4 a4 = *reinterpret_cast<const float4*>(&As[k][r * 4]);
            const float4 b4 = *reinterpret_cast<const float4*>(&Bs[k][cm * 4]);
            const float a[4] = {a4.x, a4.y, a4.z, a4.w};
            const float b[4] = {b4.x, b4.y, b4.z, b4.w};
#pragma unroll
            for (int i = 0; i < 4; ++i)
#pragma unroll
                for (int j = 0; j < 4; ++j) acc[i][j] += a[i] * b[j];
        }
        __syncthreads();
    }
    const float scale = 0.088388347648318447f;  // 1/sqrt(128)
#pragma unroll
    for (int i = 0; i < 4; ++i) {
        const int n = g_perm[p0 + r * 4 + i];
#pragma unroll
        for (int j = 0; j < 4; ++j) {
            const int m = m0 + cm * 4 + j;
            const float v = acc[i][j] * scale;
            if (z == 0)
                out[n * 512 + m] = v + bias[m];
            else
                out[n * 512 + 128 + m * 3 + (z - 1)] = v;
        }
    }
}

// ---------------- launch ---------------------------------------------------------
extern "C" void kernel_launch(void* const* d_in, const int* in_sizes, int n_in,
                              void* d_out, int out_size) {
    const float* x     = (const float*)d_in[0];
    const int*   spec  = (const int*)d_in[1];
    const float* U3_0e = (const float*)d_in[2];
    const float* U2_0e = (const float*)d_in[3];
    const float* U1_0e = (const float*)d_in[4];
    const float* W3_0e = (const float*)d_in[5];
    const float* W2_0e = (const float*)d_in[6];
    const float* W1_0e = (const float*)d_in[7];
    const float* U3_1o = (const float*)d_in[8];
    const float* U2_1o = (const float*)d_in[9];
    const float* U1_1o = (const float*)d_in[10];
    const float* W3_1o = (const float*)d_in[11];
    const float* W2_1o = (const float*)d_in[12];
    const float* W1_1o = (const float*)d_in[13];
    const float* Wl0   = (const float*)d_in[14];
    const float* Wl1   = (const float*)d_in[15];
    const float* bias  = (const float*)d_in[16];
    float* out = (float*)d_out;

    bucket_kernel<<<1, 1024>>>(spec);
    sym_kernel<<<1, 256>>>(U3_0e, U3_1o, U2_0e, U2_1o, U1_0e, U1_1o);
    transpose_kernel<<<dim3(NN / 32, CC * NELLD / 32), dim3(32, 8)>>>(x);
    precompute_kernel<<<dim3(CC, NSPEC), 256>>>(W3_0e, W2_0e, W1_0e,
                                                W3_1o, W2_1o, W1_1o);
    contract_kernel<<<dim3(NN / 256, CC), 256>>>();
    linear_kernel<<<dim3(NN / 64, 2, 4), 256>>>(Wl0, Wl1, bias, out);
}

// round 11
// speedup vs baseline: 1.3712x; 1.0711x over previous
#include <cuda_runtime.h>
#include <cstdint>

#define NN 4096
#define CC 128
#define NELLD 9
#define NSPEC 10
#define NS3 165   /* #monomials p<=q<=i over 9 */
#define NS2 45    /* #monomials p<=q */
#define NSLOT (NS3 + NS2 + 9)  /* 219 */
#define USTRIDE 876  /* floats per (c,s): 219*4 */

// ---------------- device scratch (no runtime allocation allowed) ----------------
__device__ float g_u[CC * NSPEC * USTRIDE];   // ~4.5 MB: weighted basis per (c,s), [slot][o4]
__device__ float g_xT[CC * NELLD * NN];       // ~18.9 MB: x transposed to [c][i][pos]
__device__ float g_f[4 * CC * NN];            // ~8.4 MB: contraction output [o][c][pos]
__device__ float g_u3s[16 * NS3];             // symmetrized U3, TRANSPOSED [o*4+k][slot]
__device__ float g_u2s[8 * NS2];              // symmetrized U2, TRANSPOSED [o*2+k][slot]
__device__ float g_u1s[4 * 9];                // U1 [o][p]
__device__ int   g_perm[NN];                  // pos -> node (species-sorted)
__device__ int   g_pspec[NN];                 // pos -> species

// ---------------- kernel 1: setup = bucket (block 0) + symmetrize (block 1) -----
__global__ void __launch_bounds__(1024) setup_kernel(
    const int* __restrict__ spec,
    const float* __restrict__ U3_0e, const float* __restrict__ U3_1o,
    const float* __restrict__ U2_0e, const float* __restrict__ U2_1o,
    const float* __restrict__ U1_0e, const float* __restrict__ U1_1o) {
    const int tid = threadIdx.x;
    if (blockIdx.x == 0) {
        __shared__ int cnt[NSPEC];
        __shared__ int cur[NSPEC];
        if (tid < NSPEC) cnt[tid] = 0;
        __syncthreads();
        for (int i = tid; i < NN; i += blockDim.x) atomicAdd(&cnt[spec[i]], 1);
        __syncthreads();
        if (tid == 0) {
            int off = 0;
            for (int s = 0; s < NSPEC; ++s) { cur[s] = off; off += cnt[s]; }
        }
        __syncthreads();
        for (int i = tid; i < NN; i += blockDim.x) {
            const int s = spec[i];
            const int pos = atomicAdd(&cur[s], 1);
            g_perm[pos] = i;
            g_pspec[pos] = s;
        }
        return;
    }
    // ---- symmetrize U3/U2, TRANSPOSED output [j][slot] ----
    for (int slot = tid; slot < NS3; slot += blockDim.x) {
        int t = slot, p = 0, q, i;
        for (p = 0; p < 9; ++p) { int m = 9 - p; int n = m * (m + 1) / 2; if (t < n) break; t -= n; }
        for (q = p; q < 9; ++q) { int n = 9 - q; if (t < n) break; t -= n; }
        i = q + t;
        int pa[6], pb[6], pc[6], np;
        if (p == q && q == i) { np = 1; pa[0] = p; pb[0] = q; pc[0] = i; }
        else if (p == q) { np = 3; pa[0]=p;pb[0]=p;pc[0]=i; pa[1]=p;pb[1]=i;pc[1]=p; pa[2]=i;pb[2]=p;pc[2]=p; }
        else if (q == i) { np = 3; pa[0]=p;pb[0]=q;pc[0]=q; pa[1]=q;pb[1]=p;pc[1]=q; pa[2]=q;pb[2]=q;pc[2]=p; }
        else { np = 6;
            pa[0]=p;pb[0]=q;pc[0]=i; pa[1]=p;pb[1]=i;pc[1]=q;
            pa[2]=q;pb[2]=p;pc[2]=i; pa[3]=q;pb[3]=i;pc[3]=p;
            pa[4]=i;pb[4]=p;pc[4]=q; pa[5]=i;pb[5]=q;pc[5]=p; }
        for (int o = 0; o < 4; ++o) {
            for (int k = 0; k < 4; ++k) {
                float acc = 0.f;
                for (int e = 0; e < np; ++e) {
                    int base = (pa[e] * 81 + pb[e] * 9 + pc[e]) * 4 + k;
                    acc += (o == 0) ? U3_0e[base] : U3_1o[(o - 1) * 729 * 4 + base];
                }
                g_u3s[(o * 4 + k) * NS3 + slot] = acc;
            }
        }
    }
    for (int slot = tid; slot < NS2; slot += blockDim.x) {
        int t = slot, p, q;
        for (p = 0; p < 9; ++p) { int n = 9 - p; if (t < n) break; t -= n; }
        q = p + t;
        for (int o = 0; o < 4; ++o) {
            for (int k = 0; k < 2; ++k) {
                float acc;
                if (o == 0) {
                    acc = U2_0e[(p * 9 + q) * 2 + k];
                    if (p != q) acc += U2_0e[(q * 9 + p) * 2 + k];
                } else {
                    acc = U2_1o[((o - 1) * 81 + p * 9 + q) * 2 + k];
                    if (p != q) acc += U2_1o[((o - 1) * 81 + q * 9 + p) * 2 + k];
                }
                g_u2s[(o * 2 + k) * NS2 + slot] = acc;
            }
        }
    }
    for (int pp = tid; pp < 9; pp += blockDim.x) {
        g_u1s[0 * 9 + pp] = U1_0e[pp];
        g_u1s[1 * 9 + pp] = U1_1o[pp];
        g_u1s[2 * 9 + pp] = U1_1o[9 + pp];
        g_u1s[3 * 9 + pp] = U1_1o[18 + pp];
    }
}

// ---------------- kernel 1c: gather-transpose x -> xT[c*9+i][pos] ---------------
__global__ void transpose_kernel(const float* __restrict__ x) {
    __shared__ float tile[32][33];
    const int pos0 = blockIdx.x * 32;
    const int ci0 = blockIdx.y * 32;
#pragma unroll
    for (int r = threadIdx.y; r < 32; r += 8) {
        const int n = g_perm[pos0 + r];
        tile[r][threadIdx.x] = x[(long)n * (CC * NELLD) + ci0 + threadIdx.x];
    }
    __syncthreads();
#pragma unroll
    for (int r = threadIdx.y; r < 32; r += 8)
        g_xT[(long)(ci0 + r) * NN + pos0 + threadIdx.x] = tile[threadIdx.x][r];
}

// ---------------- kernel 2: precontract, one block per (channel, species) -------
__global__ void __launch_bounds__(256) precompute_kernel(
    const float* __restrict__ W3_0e, const float* __restrict__ W2_0e, const float* __restrict__ W1_0e,
    const float* __restrict__ W3_1o, const float* __restrict__ W2_1o, const float* __restrict__ W1_1o) {
    const int c = blockIdx.x, s = blockIdx.y;
    const int t = threadIdx.x;
    if (t >= NSLOT) return;
    float4 v;
    if (t < NS3) {
        const float wa0 = W3_0e[(s * 4 + 0) * CC + c], wa1 = W3_0e[(s * 4 + 1) * CC + c];
        const float wa2 = W3_0e[(s * 4 + 2) * CC + c], wa3 = W3_0e[(s * 4 + 3) * CC + c];
        const float wb0 = W3_1o[(s * 4 + 0) * CC + c], wb1 = W3_1o[(s * 4 + 1) * CC + c];
        const float wb2 = W3_1o[(s * 4 + 2) * CC + c], wb3 = W3_1o[(s * 4 + 3) * CC + c];
        v.x = g_u3s[t] * wa0 + g_u3s[NS3 + t] * wa1 + g_u3s[2 * NS3 + t] * wa2 + g_u3s[3 * NS3 + t] * wa3;
        v.y = g_u3s[4 * NS3 + t] * wb0 + g_u3s[5 * NS3 + t] * wb1 + g_u3s[6 * NS3 + t] * wb2 + g_u3s[7 * NS3 + t] * wb3;
        v.z = g_u3s[8 * NS3 + t] * wb0 + g_u3s[9 * NS3 + t] * wb1 + g_u3s[10 * NS3 + t] * wb2 + g_u3s[11 * NS3 + t] * wb3;
        v.w = g_u3s[12 * NS3 + t] * wb0 + g_u3s[13 * NS3 + t] * wb1 + g_u3s[14 * NS3 + t] * wb2 + g_u3s[15 * NS3 + t] * wb3;
    } else if (t < NS3 + NS2) {
        const int t2 = t - NS3;
        const float wa0 = W2_0e[(s * 2 + 0) * CC + c], wa1 = W2_0e[(s * 2 + 1) * CC + c];
        const float wb0 = W2_1o[(s * 2 + 0) * CC + c], wb1 = W2_1o[(s * 2 + 1) * CC + c];
        v.x = g_u2s[t2] * wa0 + g_u2s[NS2 + t2] * wa1;
        v.y = g_u2s[2 * NS2 + t2] * wb0 + g_u2s[3 * NS2 + t2] * wb1;
        v.z = g_u2s[4 * NS2 + t2] * wb0 + g_u2s[5 * NS2 + t2] * wb1;
        v.w = g_u2s[6 * NS2 + t2] * wb0 + g_u2s[7 * NS2 + t2] * wb1;
    } else {
        const int t1 = t - NS3 - NS2;
        const float wa = W1_0e[s * CC + c];
        const float wb = W1_1o[s * CC + c];
        v = make_float4(g_u1s[t1] * wa, g_u1s[9 + t1] * wb, g_u1s[18 + t1] * wb, g_u1s[27 + t1] * wb);
    }
    reinterpret_cast<float4*>(g_u + (c * NSPEC + s) * USTRIDE)[t] = v;
}

// ---------------- kernel 3: symmetric cubic-form contraction (unchanged) --------
__global__ void __launch_bounds__(256, 4) contract_kernel() {
    const int c = blockIdx.y;
    __shared__ __align__(16) float su[NSPEC * USTRIDE];

    const float* src = g_u + c * (NSPEC * USTRIDE);
    for (int i = threadIdx.x; i < NSPEC * USTRIDE / 4; i += 256)
        reinterpret_cast<float4*>(su)[i] = reinterpret_cast<const float4*>(src)[i];
    __syncthreads();

    const int pos = blockIdx.x * 256 + threadIdx.x;
    const int s = g_pspec[pos];

    const float4* u3 = reinterpret_cast<const float4*>(su + s * USTRIDE);
    const float4* u2 = u3 + NS3;
    const float4* u1 = u2 + NS2;

    float xr[9];
#pragma unroll
    for (int i = 0; i < 9; ++i) xr[i] = g_xT[(c * 9 + i) * NN + pos];

    float acc[4] = {};
    int s3 = 0, s2 = 0;
#pragma unroll
    for (int p = 0; p < 9; ++p) {
        const float4 v1 = u1[p];
        acc[0] += v1.x * xr[p];
        acc[1] += v1.y * xr[p];
        acc[2] += v1.z * xr[p];
        acc[3] += v1.w * xr[p];
#pragma unroll
        for (int q = p; q < 9; ++q) {
            const float m2 = xr[p] * xr[q];
            const float4 v2 = u2[s2];
            ++s2;
            acc[0] += v2.x * m2;
            acc[1] += v2.y * m2;
            acc[2] += v2.z * m2;
            acc[3] += v2.w * m2;
#pragma unroll
            for (int i = q; i < 9; ++i) {
                const float4 v3 = u3[s3];
                ++s3;
                const float m = m2 * xr[i];
                acc[0] += v3.x * m;
                acc[1] += v3.y * m;
                acc[2] += v3.z * m;
                acc[3] += v3.w * m;
            }
        }
    }
#pragma unroll
    for (int o = 0; o < 4; ++o)
        g_f[(o * CC + c) * NN + pos] = acc[o];
}

// ---------------- kernel 4: e3nn Linear, register-prefetch double buffer --------
// 64pos x 64m tile, 4x4 micro, k-chunk 64 (2 iterations); next chunk prefetched
// into registers while current chunk computes from smem.
__global__ void __launch_bounds__(256) linear_kernel(
    const float* __restrict__ W0, const float* __restrict__ W1,
    const float* __restrict__ bias, float* __restrict__ out) {
    const int z = blockIdx.z;
    const int m0 = blockIdx.y * 64;
    const int p0 = blockIdx.x * 64;
    const float* A = g_f + z * (CC * NN);      // [c][pos]
    const float* B = (z == 0) ? W0 : W1;       // [c][m]
    __shared__ float As[64][64];
    __shared__ float Bs[64][64];
    const int tid = threadIdx.x;
    const int r = tid >> 4;            // 0..15 : pos-group of 4
    const int cm = tid & 15;           // 0..15 : m-group of 4
    const int lr = tid >> 4, lc = (tid & 15) << 2;  // load: row r + u*16, col*4

    float4 a_reg[4], b_reg[4];
#pragma unroll
    for (int u = 0; u < 4; ++u) {
        a_reg[u] = *reinterpret_cast<const float4*>(A + (lr + u * 16) * NN + p0 + lc);
        b_reg[u] = *reinterpret_cast<const float4*>(B + (lr + u * 16) * CC + m0 + lc);
    }

    float acc[4][4] = {};
#pragma unroll
    for (int kc = 0; kc < CC; kc += 64) {
#pragma unroll
        for (int u = 0; u < 4; ++u) {
            *reinterpret_cast<float4*>(&As[lr + u * 16][lc]) = a_reg[u];
            *reinterpret_cast<float4*>(&Bs[lr + u * 16][lc]) = b_reg[u];
        }
        __syncthreads();
        if (kc + 64 < CC) {
#pragma unroll
            for (int u = 0; u < 4; ++u) {
                a_reg[u] = *reinterpret_cast<const float4*>(A + (kc + 64 + lr + u * 16) * NN + p0 + lc);
                b_reg[u] = *reinterpret_cast<const float4*>(B + (kc + 64 + lr + u * 16) * CC + m0 + lc);
            }
        }
#pragma unroll 16
        for (int k = 0; k < 64; ++k) {
            const float4 a4 = *reinterpret_cast<const float4*>(&As[k][r * 4]);
            const float4 b4 = *reinterpret_cast<const float4*>(&Bs[k][cm * 4]);
            const float a[4] = {a4.x, a4.y, a4.z, a4.w};
            const float b[4] = {b4.x, b4.y, b4.z, b4.w};
#pragma unroll
            for (int i = 0; i < 4; ++i)
#pragma unroll
                for (int j = 0; j < 4; ++j) acc[i][j] += a[i] * b[j];
        }
        __syncthreads();
    }
    const float scale = 0.088388347648318447f;  // 1/sqrt(128)
#pragma unroll
    for (int i = 0; i < 4; ++i) {
        const int n = g_perm[p0 + r * 4 + i];
#pragma unroll
        for (int j = 0; j < 4; ++j) {
            const int m = m0 + cm * 4 + j;
            const float v = acc[i][j] * scale;
            if (z == 0)
                out[n * 512 + m] = v + bias[m];
            else
                out[n * 512 + 128 + m * 3 + (z - 1)] = v;
        }
    }
}

// ---------------- launch ---------------------------------------------------------
extern "C" void kernel_launch(void* const* d_in, const int* in_sizes, int n_in,
                              void* d_out, int out_size) {
    const float* x     = (const float*)d_in[0];
    const int*   spec  = (const int*)d_in[1];
    const float* U3_0e = (const float*)d_in[2];
    const float* U2_0e = (const float*)d_in[3];
    const float* U1_0e = (const float*)d_in[4];
    const float* W3_0e = (const float*)d_in[5];
    const float* W2_0e = (const float*)d_in[6];
    const float* W1_0e = (const float*)d_in[7];
    const float* U3_1o = (const float*)d_in[8];
    const float* U2_1o = (const float*)d_in[9];
    const float* U1_1o = (const float*)d_in[10];
    const float* W3_1o = (const float*)d_in[11];
    const float* W2_1o = (const float*)d_in[12];
    const float* W1_1o = (const float*)d_in[13];
    const float* Wl0   = (const float*)d_in[14];
    const float* Wl1   = (const float*)d_in[15];
    const float* bias  = (const float*)d_in[16];
    float* out = (float*)d_out;

    setup_kernel<<<2, 1024>>>(spec, U3_0e, U3_1o, U2_0e, U2_1o, U1_0e, U1_1o);
    transpose_kernel<<<dim3(NN / 32, CC * NELLD / 32), dim3(32, 8)>>>(x);
    precompute_kernel<<<dim3(CC, NSPEC), 256>>>(W3_0e, W2_0e, W1_0e,
                                                W3_1o, W2_1o, W1_1o);
    contract_kernel<<<dim3(NN / 256, CC), 256>>>();
    linear_kernel<<<dim3(NN / 64, 2, 4), 256>>>(Wl0, Wl1, bias, out);
}